// round 1
// baseline (speedup 1.0000x reference)
#include <cuda_runtime.h>
#include <math.h>

#define NQ 4
#define SLEN 256
#define BATCH 16384
#define PI_F 3.14159265358979323846f
#define R2_F 0.70710678118654752440f

// Precomputed Rot matrices: [ansatz(2)][layer(2)][qubit(4)][8 floats: ar,ai,br,bi,dr,di,er,ei]
__device__ float g_rot[128];

__global__ void setup_kernel(const float* __restrict__ p1, const float* __restrict__ p2) {
    int t = threadIdx.x;
    if (t >= 16) return;
    int a = t >> 3, l = (t >> 2) & 1, q = t & 3;
    const float* p = a ? p2 : p1;
    float phi = p[l * 12 + q * 3 + 0];
    float th  = p[l * 12 + q * 3 + 1];
    float om  = p[l * 12 + q * 3 + 2];
    float st, ct; sincosf(0.5f * th, &st, &ct);
    float sp, cp; sincosf(0.5f * (phi + om), &sp, &cp);
    float sm, cm; sincosf(0.5f * (phi - om), &sm, &cm);
    float* o = g_rot + t * 8;
    // a = exp(-0.5i(phi+om)) * c
    o[0] = cp * ct;  o[1] = -sp * ct;
    // b = -exp(0.5i(phi-om)) * s
    o[2] = -cm * st; o[3] = -sm * st;
    // d = exp(-0.5i(phi-om)) * s
    o[4] = cm * st;  o[5] = -sm * st;
    // e = exp(0.5i(phi+om)) * c
    o[6] = cp * ct;  o[7] = sp * ct;
}

// ---------------- gates (all compile-time masks; state lives in registers) ----------------

template <int M>
__device__ __forceinline__ void gateH(float* sr, float* si) {
#pragma unroll
    for (int i = 0; i < 16; i++) {
        if (!(i & M)) {
            const int j = i | M;
            float ar = sr[i], ai = si[i], br = sr[j], bi = si[j];
            sr[i] = (ar + br) * R2_F; si[i] = (ai + bi) * R2_F;
            sr[j] = (ar - br) * R2_F; si[j] = (ai - bi) * R2_F;
        }
    }
}

// RZ(theta): bit0 amps *= (c, -s); bit1 amps *= (c, s)   [c=cos(t/2), s=sin(t/2)]
template <int M>
__device__ __forceinline__ void gateRZ(float* sr, float* si, float c, float s) {
#pragma unroll
    for (int i = 0; i < 16; i++) {
        float sg = (i & M) ? s : -s;
        float r = sr[i], im = si[i];
        sr[i] = r * c - im * sg;
        si[i] = r * sg + im * c;
    }
}

// ZZ(theta): bits equal -> (c,-s) else (c,s)
template <int MA, int MB>
__device__ __forceinline__ void gateZZ(float* sr, float* si, float c, float s) {
#pragma unroll
    for (int i = 0; i < 16; i++) {
        bool diff = (((i & MA) != 0) != ((i & MB) != 0));
        float sg = diff ? s : -s;
        float r = sr[i], im = si[i];
        sr[i] = r * c - im * sg;
        si[i] = r * sg + im * c;
    }
}

// General 1q gate [[a,b],[d,e]] (complex); m0=(ar,ai,br,bi) m1=(dr,di,er,ei)
template <int M>
__device__ __forceinline__ void gateRot(float* sr, float* si, float4 m0, float4 m1) {
#pragma unroll
    for (int i = 0; i < 16; i++) {
        if (!(i & M)) {
            const int j = i | M;
            float x0r = sr[i], x0i = si[i], x1r = sr[j], x1i = si[j];
            sr[i] = m0.x * x0r - m0.y * x0i + m0.z * x1r - m0.w * x1i;
            si[i] = m0.x * x0i + m0.y * x0r + m0.z * x1i + m0.w * x1r;
            sr[j] = m1.x * x0r - m1.y * x0i + m1.z * x1r - m1.w * x1i;
            si[j] = m1.x * x0i + m1.y * x0r + m1.z * x1i + m1.w * x1r;
        }
    }
}

template <int MC, int MT>
__device__ __forceinline__ void gateCNOT(float* sr, float* si) {
#pragma unroll
    for (int i = 0; i < 16; i++) {
        if ((i & MC) && !(i & MT)) {
            const int j = i | MT;
            float tr = sr[i]; sr[i] = sr[j]; sr[j] = tr;
            float ti = si[i]; si[i] = si[j]; si[j] = ti;
        }
    }
}

// 7-angle diagonal block of the feature map (RZ x4 + ZZ x3)
__device__ __forceinline__ void diag7(float* sr, float* si, const float* ang) {
    float c, s;
    sincosf(0.5f * ang[0], &s, &c); gateRZ<8>(sr, si, c, s);
    sincosf(0.5f * ang[1], &s, &c); gateRZ<4>(sr, si, c, s);
    sincosf(0.5f * ang[2], &s, &c); gateRZ<2>(sr, si, c, s);
    sincosf(0.5f * ang[3], &s, &c); gateRZ<1>(sr, si, c, s);
    sincosf(0.5f * ang[4], &s, &c); gateZZ<8, 4>(sr, si, c, s);
    sincosf(0.5f * ang[5], &s, &c); gateZZ<4, 2>(sr, si, c, s);
    sincosf(0.5f * ang[6], &s, &c); gateZZ<2, 1>(sr, si, c, s);
}

// StronglyEntanglingLayers: 2 x (Rot per qubit + CNOT ring). rm -> 64 floats.
__device__ __forceinline__ void ansatz(float* sr, float* si, const float* rm) {
#pragma unroll
    for (int l = 0; l < 2; l++) {
        const float4* m = reinterpret_cast<const float4*>(rm + l * 32);
        gateRot<8>(sr, si, m[0], m[1]);
        gateRot<4>(sr, si, m[2], m[3]);
        gateRot<2>(sr, si, m[4], m[5]);
        gateRot<1>(sr, si, m[6], m[7]);
        gateCNOT<8, 4>(sr, si);
        gateCNOT<4, 2>(sr, si);
        gateCNOT<2, 1>(sr, si);
        gateCNOT<1, 8>(sr, si);
    }
}

// One quantum cell: |0000> -> FM(h) -> A1 -> FM(x) -> A2 -> <Z_q>
__device__ __forceinline__ void qcell(const float* h_ang, const float* x_ang,
                                      const float* s_rot, float* ev) {
    float sr[16], si[16];
    // |0000> through H^4 = uniform 0.25 (real) -> only the diagonal part of FM1 remains
#pragma unroll
    for (int i = 0; i < 16; i++) { sr[i] = 0.25f; si[i] = 0.0f; }
    diag7(sr, si, h_ang);
    ansatz(sr, si, s_rot);          // ansatz 1
    gateH<8>(sr, si); gateH<4>(sr, si); gateH<2>(sr, si); gateH<1>(sr, si);
    diag7(sr, si, x_ang);
    ansatz(sr, si, s_rot + 64);     // ansatz 2
    float e0 = 0.f, e1 = 0.f, e2 = 0.f, e3 = 0.f;
#pragma unroll
    for (int i = 0; i < 16; i++) {
        float p = sr[i] * sr[i] + si[i] * si[i];
        e0 += (i & 8) ? -p : p;
        e1 += (i & 4) ? -p : p;
        e2 += (i & 2) ? -p : p;
        e3 += (i & 1) ? -p : p;
    }
    ev[0] = e0; ev[1] = e1; ev[2] = e2; ev[3] = e3;
}

// KAN grid (grid_size=1, order=3, range [-1,1], h=2): [-7,-5,-3,-1,1,3,5,7]
__device__ __forceinline__ float kgrid(int j) {
    return -7.0f + 2.0f * (float)j;
}

__device__ __forceinline__ void kan_forward(const float* hid, const float* s_base,
                                            const float* s_spline, float* oang) {
    float bs[4][4];
    float sl[4];
#pragma unroll
    for (int in = 0; in < 4; in++) {
        float x = hid[in];
        sl[in] = x / (1.0f + expf(-x));   // silu
        float b0[7];
#pragma unroll
        for (int j = 0; j < 7; j++)
            b0[j] = (x >= kgrid(j) && x < kgrid(j + 1)) ? 1.0f : 0.0f;
        float b1[6];
#pragma unroll
        for (int j = 0; j < 6; j++)
            b1[j] = (x - kgrid(j)) * 0.5f * b0[j] + (kgrid(j + 2) - x) * 0.5f * b0[j + 1];
        float b2[5];
#pragma unroll
        for (int j = 0; j < 5; j++)
            b2[j] = (x - kgrid(j)) * 0.25f * b1[j] + (kgrid(j + 3) - x) * 0.25f * b1[j + 1];
#pragma unroll
        for (int j = 0; j < 4; j++)
            bs[in][j] = (x - kgrid(j)) * (1.0f / 6.0f) * b2[j]
                      + (kgrid(j + 4) - x) * (1.0f / 6.0f) * b2[j + 1];
    }
#pragma unroll
    for (int o = 0; o < 7; o++) {
        float acc = 0.0f;
#pragma unroll
        for (int in = 0; in < 4; in++)
            acc += s_base[o * 4 + in] * sl[in];
#pragma unroll
        for (int in = 0; in < 4; in++)
#pragma unroll
            for (int j = 0; j < 4; j++)
                acc += s_spline[o * 16 + in * 4 + j] * bs[in][j];
        oang[o] = acc;
    }
}

__global__ void __launch_bounds__(128, 1) qrnn_kernel(
    const float* __restrict__ inputs,      // [B, S, 4]
    const float* __restrict__ initial_t,   // [B, 7]
    const float* __restrict__ base_w,      // [7, 4]
    const float* __restrict__ spline_w,    // [7, 4, 4]
    const float* __restrict__ cw1,         // [16, 4]
    const float* __restrict__ cb1,         // [16]
    const float* __restrict__ cw2,         // [1, 16]
    const float* __restrict__ cb2,         // [1]
    float* __restrict__ out)               // [B]
{
    __shared__ __align__(16) float s_rot[128];
    __shared__ float s_base[28];
    __shared__ float s_spline[112];
    int tid = threadIdx.x;
    if (tid < 128) s_rot[tid] = g_rot[tid];
    if (tid < 28)  s_base[tid] = base_w[tid];
    if (tid < 112) s_spline[tid] = spline_w[tid];
    __syncthreads();

    int b = blockIdx.x * blockDim.x + tid;

    float h_ang[7];
#pragma unroll
    for (int k = 0; k < 7; k++) h_ang[k] = initial_t[b * 7 + k];

    const float4* inp = reinterpret_cast<const float4*>(inputs) + (size_t)b * SLEN;

    float hid[4];
#pragma unroll 1
    for (int t = 0; t < SLEN; t++) {
        float4 xv = inp[t];
        float x_ang[7];
        x_ang[0] = xv.x; x_ang[1] = xv.y; x_ang[2] = xv.z; x_ang[3] = xv.w;
        x_ang[4] = (PI_F - xv.x) * (PI_F - xv.y);
        x_ang[5] = (PI_F - xv.y) * (PI_F - xv.z);
        x_ang[6] = (PI_F - xv.z) * (PI_F - xv.w);
        if (t > 0) kan_forward(hid, s_base, s_spline, h_ang);
        qcell(h_ang, x_ang, s_rot, hid);
    }

    // classifier: relu(hid @ W1^T + b1) @ W2^T + b2
    float o = cb2[0];
#pragma unroll 1
    for (int k = 0; k < 16; k++) {
        float a = cb1[k];
        a += cw1[k * 4 + 0] * hid[0];
        a += cw1[k * 4 + 1] * hid[1];
        a += cw1[k * 4 + 2] * hid[2];
        a += cw1[k * 4 + 3] * hid[3];
        o += cw2[k] * fmaxf(a, 0.0f);
    }
    out[b] = o;
}

extern "C" void kernel_launch(void* const* d_in, const int* in_sizes, int n_in,
                              void* d_out, int out_size) {
    const float* inputs    = (const float*)d_in[0];
    const float* initial_t = (const float*)d_in[1];
    const float* p1        = (const float*)d_in[2];
    const float* p2        = (const float*)d_in[3];
    const float* base_w    = (const float*)d_in[4];
    const float* spline_w  = (const float*)d_in[5];
    const float* cw1       = (const float*)d_in[6];
    const float* cb1       = (const float*)d_in[7];
    const float* cw2       = (const float*)d_in[8];
    const float* cb2       = (const float*)d_in[9];

    setup_kernel<<<1, 16>>>(p1, p2);
    qrnn_kernel<<<BATCH / 128, 128>>>(inputs, initial_t, base_w, spline_w,
                                      cw1, cb1, cw2, cb2, (float*)d_out);
}

// round 2
// speedup vs baseline: 2.1347x; 2.1347x over previous
#include <cuda_runtime.h>
#include <math.h>

#define SLEN 256
#define BATCH 16384
#define PI_F 3.14159265358979323846f
#define R2_F 0.70710678118654752440f

typedef unsigned long long ull;

// ---------- packed f32x2 primitives ----------
__device__ __forceinline__ ull F2MUL(ull a, ull b) {
    ull d; asm("mul.rn.f32x2 %0,%1,%2;" : "=l"(d) : "l"(a), "l"(b)); return d;
}
__device__ __forceinline__ ull F2FMA(ull a, ull b, ull c) {
    ull d; asm("fma.rn.f32x2 %0,%1,%2,%3;" : "=l"(d) : "l"(a), "l"(b), "l"(c)); return d;
}
__device__ __forceinline__ ull F2ADD(ull a, ull b) {
    ull d; asm("add.rn.f32x2 %0,%1,%2;" : "=l"(d) : "l"(a), "l"(b)); return d;
}
__device__ __forceinline__ ull PACK2(float lo, float hi) {
    ull d; asm("mov.b64 %0,{%1,%2};" : "=l"(d) : "f"(lo), "f"(hi)); return d;
}
__device__ __forceinline__ float2 UNPK(ull v) {
    float2 r; asm("mov.b64 {%0,%1},%2;" : "=f"(r.x), "=f"(r.y) : "l"(v)); return r;
}
__device__ __forceinline__ ull SWAPH(ull v) {
    float2 r = UNPK(v); return PACK2(r.y, r.x);
}

// Packed gate constants: 16 Rot matrices x 12 slots (float2 each)
__device__ float2 g_rotc[192];
// KAN folded weights: 7 outputs x 20 (base[4], c1[4], c2[4], c3[4], c0sum, pad)
__device__ float g_kan[140];

__global__ void setup_kernel(const float* __restrict__ p1, const float* __restrict__ p2,
                             const float* __restrict__ base_w, const float* __restrict__ spline_w) {
    int t = threadIdx.x;
    if (t < 16) {
        int a = t >> 3, l = (t >> 2) & 1, q = t & 3;
        const float* p = a ? p2 : p1;
        float phi = p[l * 12 + q * 3 + 0];
        float th  = p[l * 12 + q * 3 + 1];
        float om  = p[l * 12 + q * 3 + 2];
        float st, ct; sincosf(0.5f * th, &st, &ct);
        float sp, cp; sincosf(0.5f * (phi + om), &sp, &cp);
        float sm, cm; sincosf(0.5f * (phi - om), &sm, &cm);
        float ar =  cp * ct, ai = -sp * ct;
        float br = -cm * st, bi = -sm * st;
        float dr =  cm * st, di = -sm * st;
        float er =  cp * ct, ei =  sp * ct;
        float2* o = g_rotc + t * 12;
        if (q < 3) {
            o[0]  = make_float2(ar, ar);   o[1]  = make_float2(-ai, -ai);
            o[2]  = make_float2(br, br);   o[3]  = make_float2(-bi, -bi);
            o[4]  = make_float2(ai, ai);   o[5]  = make_float2(bi, bi);
            o[6]  = make_float2(dr, dr);   o[7]  = make_float2(-di, -di);
            o[8]  = make_float2(er, er);   o[9]  = make_float2(-ei, -ei);
            o[10] = make_float2(di, di);   o[11] = make_float2(ei, ei);
        } else {
            // lane-mixed constants for qubit-3 rotation
            o[0] = make_float2(ar, er);    // CA
            o[1] = make_float2(br, dr);    // CB
            o[2] = make_float2(-ai, -ei);  // CC
            o[3] = make_float2(-bi, -di);  // CD
            o[4] = make_float2(ai, ei);    // CE
            o[5] = make_float2(bi, di);    // CF
            for (int j = 6; j < 12; j++) o[j] = make_float2(0.f, 0.f);
        }
    }
    if (t == 16) {
        // B-spline bases on the interior interval [-1,1) collapse to cubics:
        // bs_j(x) = (BP[j][0] + BP[j][1] x + BP[j][2] x^2 + BP[j][3] x^3)/48
        const float BP[4][4] = {
            {1.f, -3.f, 3.f, -1.f},
            {23.f, -15.f, -3.f, 3.f},
            {23.f, 15.f, -3.f, -3.f},
            {1.f, 3.f, 3.f, 1.f}
        };
        const float inv48 = 1.0f / 48.0f;
        for (int o = 0; o < 7; o++) {
            float c0sum = 0.f;
            for (int in = 0; in < 4; in++) {
                float P[4] = {0.f, 0.f, 0.f, 0.f};
                for (int j = 0; j < 4; j++) {
                    float w = spline_w[o * 16 + in * 4 + j] * inv48;
                    for (int k = 0; k < 4; k++) P[k] += w * BP[j][k];
                }
                g_kan[o * 20 + in]      = base_w[o * 4 + in];
                g_kan[o * 20 + 4 + in]  = P[1];
                g_kan[o * 20 + 8 + in]  = P[2];
                g_kan[o * 20 + 12 + in] = P[3];
                c0sum += P[0];
            }
            g_kan[o * 20 + 16] = c0sum;
        }
    }
}

// ---------------- packed gates ----------------
// State: R[8], I[8]; pair k holds amplitudes (2k, 2k+1); lane = qubit3 bit.
// pair-index bits: bit2=qubit0, bit1=qubit1, bit0=qubit2.

// Diagonal gate: R'=c*R - sg*I, I'=sg*R + c*I. sg per pair chosen by PAT bit.
template <int PAT>
__device__ __forceinline__ void diagG(ull* R, ull* I, ull c2, ull sp, ull sn) {
#pragma unroll
    for (int k = 0; k < 8; k++) {
        ull sg = ((PAT >> k) & 1) ? sp : sn;
        ull gs = ((PAT >> k) & 1) ? sn : sp;   // -sg
        ull xr = R[k], xi = I[k];
        R[k] = F2FMA(gs, xi, F2MUL(c2, xr));
        I[k] = F2FMA(sg, xr, F2MUL(c2, xi));
    }
}

// Lane-wise Rot on pair-mask PM (qubits 0..2)
template <int PM>
__device__ __forceinline__ void rotL(ull* R, ull* I, const ull* m) {
#pragma unroll
    for (int k = 0; k < 8; k++) {
        if (!(k & PM)) {
            const int j = k | PM;
            ull x0r = R[k], x0i = I[k], x1r = R[j], x1i = I[j];
            ull t;
            t = F2MUL(m[0], x0r); t = F2FMA(m[1], x0i, t); t = F2FMA(m[2], x1r, t); t = F2FMA(m[3], x1i, t); R[k] = t;
            t = F2MUL(m[0], x0i); t = F2FMA(m[4], x0r, t); t = F2FMA(m[2], x1i, t); t = F2FMA(m[5], x1r, t); I[k] = t;
            t = F2MUL(m[6], x0r); t = F2FMA(m[7], x0i, t); t = F2FMA(m[8], x1r, t); t = F2FMA(m[9], x1i, t); R[j] = t;
            t = F2MUL(m[6], x0i); t = F2FMA(m[10], x0r, t); t = F2FMA(m[8], x1i, t); t = F2FMA(m[11], x1r, t); I[j] = t;
        }
    }
}

// Rot on qubit 3 (the lane axis): lane-mixed constants CA..CF in m[0..5]
__device__ __forceinline__ void rot1(ull* R, ull* I, const ull* m) {
#pragma unroll
    for (int k = 0; k < 8; k++) {
        ull pr = R[k], pi = I[k];
        ull prs = SWAPH(pr), pis = SWAPH(pi);
        ull t = F2MUL(m[0], pr); t = F2FMA(m[1], prs, t); t = F2FMA(m[2], pi, t); t = F2FMA(m[3], pis, t);
        ull u = F2MUL(m[4], pr); u = F2FMA(m[5], prs, u); u = F2FMA(m[0], pi, u); u = F2FMA(m[1], pis, u);
        R[k] = t; I[k] = u;
    }
}

// Lane-wise H on pair-mask PM
template <int PM>
__device__ __forceinline__ void hL(ull* R, ull* I, ull r2p, ull nr2p) {
#pragma unroll
    for (int k = 0; k < 8; k++) {
        if (!(k & PM)) {
            const int j = k | PM;
            ull x1r = R[j], x1i = I[j];
            ull tr = F2MUL(r2p, R[k]);
            ull ti = F2MUL(r2p, I[k]);
            R[k] = F2FMA(r2p, x1r, tr);  R[j] = F2FMA(nr2p, x1r, tr);
            I[k] = F2FMA(r2p, x1i, ti);  I[j] = F2FMA(nr2p, x1i, ti);
        }
    }
}

// H on qubit 3 (lane axis): out = (r2,-r2)*x + (r2,r2)*swap(x)
__device__ __forceinline__ void h1(ull* R, ull* I, ull r2p, ull hm) {
#pragma unroll
    for (int k = 0; k < 8; k++) {
        ull pr = R[k], pi = I[k];
        R[k] = F2FMA(r2p, SWAPH(pr), F2MUL(hm, pr));
        I[k] = F2FMA(r2p, SWAPH(pi), F2MUL(hm, pi));
    }
}

__device__ __forceinline__ void cnot_ring(ull* R, ull* I) {
    // CNOT(q0,q1): pairs with bit2=1: swap k <-> k|2
    { ull t; t = R[4]; R[4] = R[6]; R[6] = t; t = I[4]; I[4] = I[6]; I[6] = t;
      t = R[5]; R[5] = R[7]; R[7] = t; t = I[5]; I[5] = I[7]; I[7] = t; }
    // CNOT(q1,q2): pairs with bit1=1: swap k <-> k|1
    { ull t; t = R[2]; R[2] = R[3]; R[3] = t; t = I[2]; I[2] = I[3]; I[3] = t;
      t = R[6]; R[6] = R[7]; R[7] = t; t = I[6]; I[6] = I[7]; I[7] = t; }
    // CNOT(q2,q3): odd pairs: swap lanes
#pragma unroll
    for (int k = 1; k < 8; k += 2) { R[k] = SWAPH(R[k]); I[k] = SWAPH(I[k]); }
    // CNOT(q3,q0): lane1 amplitudes swap across pair-bit2
#pragma unroll
    for (int k = 0; k < 4; k++) {
        float2 a = UNPK(R[k]), b = UNPK(R[k + 4]);
        R[k] = PACK2(a.x, b.y); R[k + 4] = PACK2(b.x, a.y);
        float2 c = UNPK(I[k]), d = UNPK(I[k + 4]);
        I[k] = PACK2(c.x, d.y); I[k + 4] = PACK2(d.x, c.y);
    }
}

__device__ __forceinline__ void ansatz(ull* R, ull* I, const ull* mats) {
#pragma unroll
    for (int l = 0; l < 2; l++) {
        const ull* m = mats + l * 48;
        rotL<4>(R, I, m);
        rotL<2>(R, I, m + 12);
        rotL<1>(R, I, m + 24);
        rot1(R, I, m + 36);
        cnot_ring(R, I);
    }
}

__device__ __forceinline__ void diag7(ull* R, ull* I, const float* ang) {
    float s, c;
    __sincosf(0.5f * ang[0], &s, &c);
    diagG<0xF0>(R, I, PACK2(c, c), PACK2(s, s), PACK2(-s, -s));
    __sincosf(0.5f * ang[1], &s, &c);
    diagG<0xCC>(R, I, PACK2(c, c), PACK2(s, s), PACK2(-s, -s));
    __sincosf(0.5f * ang[2], &s, &c);
    diagG<0xAA>(R, I, PACK2(c, c), PACK2(s, s), PACK2(-s, -s));
    __sincosf(0.5f * ang[3], &s, &c);
    diagG<0xFF>(R, I, PACK2(c, c), PACK2(-s, s), PACK2(s, -s));   // qubit3: lane-mixed
    __sincosf(0.5f * ang[4], &s, &c);
    diagG<0x3C>(R, I, PACK2(c, c), PACK2(s, s), PACK2(-s, -s));   // ZZ(q0,q1)
    __sincosf(0.5f * ang[5], &s, &c);
    diagG<0x66>(R, I, PACK2(c, c), PACK2(s, s), PACK2(-s, -s));   // ZZ(q1,q2)
    __sincosf(0.5f * ang[6], &s, &c);
    diagG<0x55>(R, I, PACK2(c, c), PACK2(-s, s), PACK2(s, -s));   // ZZ(q2,q3): lane-mixed
}

__device__ __forceinline__ void qcell(const float* h_ang, const float* x_ang,
                                      const ull* s_rot, float* ev) {
    ull R[8], I[8];
    ull q = PACK2(0.25f, 0.25f);
    ull z = PACK2(0.0f, 0.0f);
#pragma unroll
    for (int k = 0; k < 8; k++) { R[k] = q; I[k] = z; }
    diag7(R, I, h_ang);
    ansatz(R, I, s_rot);          // ansatz 1
    {
        ull r2p = PACK2(R2_F, R2_F), nr2p = PACK2(-R2_F, -R2_F), hm = PACK2(R2_F, -R2_F);
        hL<4>(R, I, r2p, nr2p); hL<2>(R, I, r2p, nr2p); hL<1>(R, I, r2p, nr2p);
        h1(R, I, r2p, hm);
    }
    diag7(R, I, x_ang);
    ansatz(R, I, s_rot + 96);     // ansatz 2
    // probabilities (packed) and <Z_q>
    ull p[8];
#pragma unroll
    for (int k = 0; k < 8; k++) p[k] = F2FMA(I[k], I[k], F2MUL(R[k], R[k]));
    ull n1 = PACK2(-1.f, -1.f);
    ull a = F2ADD(p[0], p[1]), b = F2ADD(p[2], p[3]);
    ull c = F2ADD(p[4], p[5]), d = F2ADD(p[6], p[7]);
    ull T1 = F2ADD(a, b), T2 = F2ADD(c, d);
    ull e0p = F2FMA(n1, T2, T1);
    ull U1 = F2ADD(a, c), U2 = F2ADD(b, d);
    ull e1p = F2FMA(n1, U2, U1);
    ull V1 = F2ADD(F2ADD(p[0], p[2]), F2ADD(p[4], p[6]));
    ull V2 = F2ADD(F2ADD(p[1], p[3]), F2ADD(p[5], p[7]));
    ull e2p = F2FMA(n1, V2, V1);
    ull T = F2ADD(T1, T2);
    float2 f;
    f = UNPK(e0p); ev[0] = f.x + f.y;
    f = UNPK(e1p); ev[1] = f.x + f.y;
    f = UNPK(e2p); ev[2] = f.x + f.y;
    f = UNPK(T);   ev[3] = f.x - f.y;
}

__device__ __forceinline__ void kan_f(const float* hid, const float* W, float* oang) {
    float sl[4], x2[4], x3[4];
#pragma unroll
    for (int in = 0; in < 4; in++) {
        float x = hid[in];
        float e = __expf(-x);
        sl[in] = __fdividef(x, 1.0f + e);
        x2[in] = x * x;
        x3[in] = x2[in] * x;
    }
#pragma unroll
    for (int o = 0; o < 7; o++) {
        const float* w = W + o * 20;
        float acc = w[16];
#pragma unroll
        for (int in = 0; in < 4; in++) acc = fmaf(w[in], sl[in], acc);
#pragma unroll
        for (int in = 0; in < 4; in++) acc = fmaf(w[4 + in], hid[in], acc);
#pragma unroll
        for (int in = 0; in < 4; in++) acc = fmaf(w[8 + in], x2[in], acc);
#pragma unroll
        for (int in = 0; in < 4; in++) acc = fmaf(w[12 + in], x3[in], acc);
        oang[o] = acc;
    }
}

__global__ void __launch_bounds__(128, 1) qrnn_kernel(
    const float* __restrict__ inputs,      // [B, S, 4]
    const float* __restrict__ initial_t,   // [B, 7]
    const float* __restrict__ cw1,         // [16, 4]
    const float* __restrict__ cb1,         // [16]
    const float* __restrict__ cw2,         // [1, 16]
    const float* __restrict__ cb2,         // [1]
    float* __restrict__ out)               // [B]
{
    __shared__ __align__(16) ull s_rot[192];
    __shared__ float s_kan[140];
    int tid = threadIdx.x;
    const ull* grc = reinterpret_cast<const ull*>(g_rotc);
    for (int i = tid; i < 192; i += 128) s_rot[i] = grc[i];
    for (int i = tid; i < 140; i += 128) s_kan[i] = g_kan[i];
    __syncthreads();

    int b = blockIdx.x * blockDim.x + tid;

    float h_ang[7];
#pragma unroll
    for (int k = 0; k < 7; k++) h_ang[k] = initial_t[b * 7 + k];

    const float4* inp = reinterpret_cast<const float4*>(inputs) + (size_t)b * SLEN;

    float hid[4];
#pragma unroll 1
    for (int t = 0; t < SLEN; t++) {
        float4 xv = inp[t];
        float x_ang[7];
        x_ang[0] = xv.x; x_ang[1] = xv.y; x_ang[2] = xv.z; x_ang[3] = xv.w;
        x_ang[4] = (PI_F - xv.x) * (PI_F - xv.y);
        x_ang[5] = (PI_F - xv.y) * (PI_F - xv.z);
        x_ang[6] = (PI_F - xv.z) * (PI_F - xv.w);
        if (t > 0) kan_f(hid, s_kan, h_ang);
        qcell(h_ang, x_ang, s_rot, hid);
    }

    float o = cb2[0];
#pragma unroll 1
    for (int k = 0; k < 16; k++) {
        float a = cb1[k];
        a = fmaf(cw1[k * 4 + 0], hid[0], a);
        a = fmaf(cw1[k * 4 + 1], hid[1], a);
        a = fmaf(cw1[k * 4 + 2], hid[2], a);
        a = fmaf(cw1[k * 4 + 3], hid[3], a);
        o = fmaf(cw2[k], fmaxf(a, 0.0f), o);
    }
    out[b] = o;
}

extern "C" void kernel_launch(void* const* d_in, const int* in_sizes, int n_in,
                              void* d_out, int out_size) {
    const float* inputs    = (const float*)d_in[0];
    const float* initial_t = (const float*)d_in[1];
    const float* p1        = (const float*)d_in[2];
    const float* p2        = (const float*)d_in[3];
    const float* base_w    = (const float*)d_in[4];
    const float* spline_w  = (const float*)d_in[5];
    const float* cw1       = (const float*)d_in[6];
    const float* cb1       = (const float*)d_in[7];
    const float* cw2       = (const float*)d_in[8];
    const float* cb2       = (const float*)d_in[9];

    setup_kernel<<<1, 32>>>(p1, p2, base_w, spline_w);
    qrnn_kernel<<<BATCH / 128, 128>>>(inputs, initial_t,
                                      cw1, cb1, cw2, cb2, (float*)d_out);
}

// round 3
// speedup vs baseline: 2.3964x; 1.1226x over previous
#include <cuda_runtime.h>
#include <math.h>

#define SLEN 256
#define BATCH 16384
#define PI_F 3.14159265358979323846f
#define R2_F 0.70710678118654752440f

typedef unsigned long long ull;

// ---------- packed f32x2 primitives ----------
__device__ __forceinline__ ull F2MUL(ull a, ull b) {
    ull d; asm("mul.rn.f32x2 %0,%1,%2;" : "=l"(d) : "l"(a), "l"(b)); return d;
}
__device__ __forceinline__ ull F2FMA(ull a, ull b, ull c) {
    ull d; asm("fma.rn.f32x2 %0,%1,%2,%3;" : "=l"(d) : "l"(a), "l"(b), "l"(c)); return d;
}
__device__ __forceinline__ ull F2ADD(ull a, ull b) {
    ull d; asm("add.rn.f32x2 %0,%1,%2;" : "=l"(d) : "l"(a), "l"(b)); return d;
}
__device__ __forceinline__ ull F2SUB(ull a, ull b) {
    ull d; asm("sub.rn.f32x2 %0,%1,%2;" : "=l"(d) : "l"(a), "l"(b)); return d;
}
__device__ __forceinline__ ull PACK2(float lo, float hi) {
    ull d; asm("mov.b64 %0,{%1,%2};" : "=l"(d) : "f"(lo), "f"(hi)); return d;
}
__device__ __forceinline__ float2 UNPK(ull v) {
    float2 r; asm("mov.b64 {%0,%1},%2;" : "=f"(r.x), "=f"(r.y) : "l"(v)); return r;
}
__device__ __forceinline__ ull SWAPH(ull v) {
    float2 r = UNPK(v); return PACK2(r.y, r.x);
}
__device__ __forceinline__ ull MIXLH(ull a, ull b) {   // (a.lo, b.hi)
    float2 x = UNPK(a), y = UNPK(b); return PACK2(x.x, y.y);
}

// Packed gate constants: 16 Rot matrices x 12 slots (float2 each).
// Layer-2 matrices are pre-multiplied by H (H-fold of the inter-ansatz H block
// applies only to ansatz 1, but both ansatz keep their own L2; only a=0,l=1 is folded).
__device__ float2 g_rotc[192];
// KAN folded weights: 7 outputs x 20 (base[4], c1[4], c2[4], c3[4], c0sum, pad)
__device__ float g_kan[140];

__global__ void setup_kernel(const float* __restrict__ p1, const float* __restrict__ p2,
                             const float* __restrict__ base_w, const float* __restrict__ spline_w) {
    int t = threadIdx.x;
    if (t < 16) {
        int a = t >> 3, l = (t >> 2) & 1, q = t & 3;
        const float* p = a ? p2 : p1;
        float phi = p[l * 12 + q * 3 + 0];
        float th  = p[l * 12 + q * 3 + 1];
        float om  = p[l * 12 + q * 3 + 2];
        float st, ct; sincosf(0.5f * th, &st, &ct);
        float sp, cp; sincosf(0.5f * (phi + om), &sp, &cp);
        float sm, cm; sincosf(0.5f * (phi - om), &sm, &cm);
        float ar =  cp * ct, ai = -sp * ct;
        float br = -cm * st, bi = -sm * st;
        float dr =  cm * st, di = -sm * st;
        float er =  cp * ct, ei =  sp * ct;
        if (a == 0 && l == 1) {
            // fold H: Rot' = H @ Rot  (rows: (a+d,b+e)/sqrt2 ; (a-d,b-e)/sqrt2)
            float nar = (ar + dr) * R2_F, nai = (ai + di) * R2_F;
            float nbr = (br + er) * R2_F, nbi = (bi + ei) * R2_F;
            float ndr = (ar - dr) * R2_F, ndi = (ai - di) * R2_F;
            float ner = (br - er) * R2_F, nei = (bi - ei) * R2_F;
            ar = nar; ai = nai; br = nbr; bi = nbi;
            dr = ndr; di = ndi; er = ner; ei = nei;
        }
        float2* o = g_rotc + t * 12;
        if (q < 3) {
            o[0]  = make_float2(ar, ar);   o[1]  = make_float2(-ai, -ai);
            o[2]  = make_float2(br, br);   o[3]  = make_float2(-bi, -bi);
            o[4]  = make_float2(ai, ai);   o[5]  = make_float2(bi, bi);
            o[6]  = make_float2(dr, dr);   o[7]  = make_float2(-di, -di);
            o[8]  = make_float2(er, er);   o[9]  = make_float2(-ei, -ei);
            o[10] = make_float2(di, di);   o[11] = make_float2(ei, ei);
        } else {
            // lane-mixed constants for qubit-3 rotation
            o[0] = make_float2(ar, er);    // CA
            o[1] = make_float2(br, dr);    // CB
            o[2] = make_float2(-ai, -ei);  // CC
            o[3] = make_float2(-bi, -di);  // CD
            o[4] = make_float2(ai, ei);    // CE
            o[5] = make_float2(bi, di);    // CF
            for (int j = 6; j < 12; j++) o[j] = make_float2(0.f, 0.f);
        }
    }
    if (t == 16) {
        // B-spline bases on [-1,1) collapse to cubics: bs_j(x) = poly/48
        const float BP[4][4] = {
            {1.f, -3.f, 3.f, -1.f},
            {23.f, -15.f, -3.f, 3.f},
            {23.f, 15.f, -3.f, -3.f},
            {1.f, 3.f, 3.f, 1.f}
        };
        const float inv48 = 1.0f / 48.0f;
        for (int o = 0; o < 7; o++) {
            float c0sum = 0.f;
            for (int in = 0; in < 4; in++) {
                float P[4] = {0.f, 0.f, 0.f, 0.f};
                for (int j = 0; j < 4; j++) {
                    float w = spline_w[o * 16 + in * 4 + j] * inv48;
                    for (int k = 0; k < 4; k++) P[k] += w * BP[j][k];
                }
                g_kan[o * 20 + in]      = base_w[o * 4 + in];
                g_kan[o * 20 + 4 + in]  = P[1];
                g_kan[o * 20 + 8 + in]  = P[2];
                g_kan[o * 20 + 12 + in] = P[3];
                c0sum += P[0];
            }
            g_kan[o * 20 + 16] = c0sum;
        }
    }
}

// ---------------- packed gates ----------------
// State: R[8], I[8]; pack lane = qubit3 bit; pair bits: bit2=q0, bit1=q1, bit0=q2.

// Lane-wise Rot on pair-mask PM (qubits 0..2)
template <int PM>
__device__ __forceinline__ void rotL(ull* R, ull* I, const ull* m) {
#pragma unroll
    for (int k = 0; k < 8; k++) {
        if (!(k & PM)) {
            const int j = k | PM;
            ull x0r = R[k], x0i = I[k], x1r = R[j], x1i = I[j];
            ull t;
            t = F2MUL(m[0], x0r); t = F2FMA(m[1], x0i, t); t = F2FMA(m[2], x1r, t); t = F2FMA(m[3], x1i, t); R[k] = t;
            t = F2MUL(m[0], x0i); t = F2FMA(m[4], x0r, t); t = F2FMA(m[2], x1i, t); t = F2FMA(m[5], x1r, t); I[k] = t;
            t = F2MUL(m[6], x0r); t = F2FMA(m[7], x0i, t); t = F2FMA(m[8], x1r, t); t = F2FMA(m[9], x1i, t); R[j] = t;
            t = F2MUL(m[6], x0i); t = F2FMA(m[10], x0r, t); t = F2FMA(m[8], x1i, t); t = F2FMA(m[11], x1r, t); I[j] = t;
        }
    }
}

// Rot on qubit 3 (lane axis): lane-mixed constants CA..CF in m[0..5]
__device__ __forceinline__ void rot1(ull* R, ull* I, const ull* m) {
#pragma unroll
    for (int k = 0; k < 8; k++) {
        ull pr = R[k], pi = I[k];
        ull prs = SWAPH(pr), pis = SWAPH(pi);
        ull t = F2MUL(m[0], pr); t = F2FMA(m[1], prs, t); t = F2FMA(m[2], pi, t); t = F2FMA(m[3], pis, t);
        ull u = F2MUL(m[4], pr); u = F2FMA(m[5], prs, u); u = F2FMA(m[0], pi, u); u = F2FMA(m[1], pis, u);
        R[k] = t; I[k] = u;
    }
}

// Standard CNOT ring: (q0,q1)(q1,q2)(q2,q3)(q3,q0)
__device__ __forceinline__ void cnot_ring(ull* R, ull* I) {
    // CNOT(q0,q1): k bit2=1: swap bit1
    { ull t; t = R[4]; R[4] = R[6]; R[6] = t; t = I[4]; I[4] = I[6]; I[6] = t;
      t = R[5]; R[5] = R[7]; R[7] = t; t = I[5]; I[5] = I[7]; I[7] = t; }
    // CNOT(q1,q2): k bit1=1: swap bit0
    { ull t; t = R[2]; R[2] = R[3]; R[3] = t; t = I[2]; I[2] = I[3]; I[3] = t;
      t = R[6]; R[6] = R[7]; R[7] = t; t = I[6]; I[6] = I[7]; I[7] = t; }
    // CNOT(q2,q3): k bit0=1: swap lanes
#pragma unroll
    for (int k = 1; k < 8; k += 2) { R[k] = SWAPH(R[k]); I[k] = SWAPH(I[k]); }
    // CNOT(q3,q0): lane1 swaps across bit2
#pragma unroll
    for (int k = 0; k < 4; k++) {
        ull nr0 = MIXLH(R[k], R[k + 4]), nr1 = MIXLH(R[k + 4], R[k]);
        R[k] = nr0; R[k + 4] = nr1;
        ull ni0 = MIXLH(I[k], I[k + 4]), ni1 = MIXLH(I[k + 4], I[k]);
        I[k] = ni0; I[k + 4] = ni1;
    }
}

// H-conjugated (reversed) ring: apply C(1,0), C(2,1), C(3,2), C(0,3)
__device__ __forceinline__ void cnot_ring_rev(ull* R, ull* I) {
    // C(1,0): k bit1=1: swap bit2: (2,6),(3,7)
    { ull t; t = R[2]; R[2] = R[6]; R[6] = t; t = I[2]; I[2] = I[6]; I[6] = t;
      t = R[3]; R[3] = R[7]; R[7] = t; t = I[3]; I[3] = I[7]; I[7] = t; }
    // C(2,1): k bit0=1: swap bit1: (1,3),(5,7)
    { ull t; t = R[1]; R[1] = R[3]; R[3] = t; t = I[1]; I[1] = I[3]; I[3] = t;
      t = R[5]; R[5] = R[7]; R[7] = t; t = I[5]; I[5] = I[7]; I[7] = t; }
    // C(3,2): lane1 swaps bit0: pairs (k, k^1), k even
#pragma unroll
    for (int k = 0; k < 8; k += 2) {
        ull nr0 = MIXLH(R[k], R[k + 1]), nr1 = MIXLH(R[k + 1], R[k]);
        R[k] = nr0; R[k + 1] = nr1;
        ull ni0 = MIXLH(I[k], I[k + 1]), ni1 = MIXLH(I[k + 1], I[k]);
        I[k] = ni0; I[k + 1] = ni1;
    }
    // C(0,3): k bit2=1: swap lanes
#pragma unroll
    for (int k = 4; k < 8; k++) { R[k] = SWAPH(R[k]); I[k] = SWAPH(I[k]); }
}

// 16 fused diagonal phases: ph[2k+lane] for pair k=(q0,q1,q2), lane=q3
__device__ __forceinline__ void phases16(const float* ang, float* ph) {
    float b0 = 0.5f * ang[0], b1 = 0.5f * ang[1], b2 = 0.5f * ang[2], b3 = 0.5f * ang[3];
    float b4 = 0.5f * ang[4], b5 = 0.5f * ang[5], b6 = 0.5f * ang[6];
    float t01 = b0 + b1, d01 = b0 - b1;
    float u00 = -t01 - b4, u01 = -d01 + b4, u10 = d01 + b4, u11 = t01 - b4;
    float t23 = b2 + b3, d23 = b2 - b3;
    float e00 = -t23 - b6, e01 = -d23 + b6, e10 = d23 + b6, e11 = t23 - b6;
    float w000 = e00 - b5, w001 = e01 - b5, w010 = e10 + b5, w011 = e11 + b5;
    float w100 = e00 + b5, w101 = e01 + b5, w110 = e10 - b5, w111 = e11 - b5;
    ph[0]  = u00 + w000; ph[1]  = u00 + w001;
    ph[2]  = u00 + w010; ph[3]  = u00 + w011;
    ph[4]  = u01 + w100; ph[5]  = u01 + w101;
    ph[6]  = u01 + w110; ph[7]  = u01 + w111;
    ph[8]  = u10 + w000; ph[9]  = u10 + w001;
    ph[10] = u10 + w010; ph[11] = u10 + w011;
    ph[12] = u11 + w100; ph[13] = u11 + w101;
    ph[14] = u11 + w110; ph[15] = u11 + w111;
}

__device__ __forceinline__ void qcell(const float* h_ang, const float* x_ang,
                                      const ull* s_rot, float* ev) {
    ull R[8], I[8];
    float ph[16];

    // D1 on uniform state: amps = e^{i phi} (scale 1/4 folded into measurement)
    phases16(h_ang, ph);
#pragma unroll
    for (int k = 0; k < 8; k++) {
        float s0, c0, s1, c1;
        __sincosf(ph[2 * k], &s0, &c0);
        __sincosf(ph[2 * k + 1], &s1, &c1);
        R[k] = PACK2(c0, c1); I[k] = PACK2(s0, s1);
    }

    // ansatz 1, layer 1 (normal ring) + layer 2 (H-folded rots, reversed ring)
    rotL<4>(R, I, s_rot);      rotL<2>(R, I, s_rot + 12);
    rotL<1>(R, I, s_rot + 24); rot1(R, I, s_rot + 36);
    cnot_ring(R, I);
    rotL<4>(R, I, s_rot + 48); rotL<2>(R, I, s_rot + 60);
    rotL<1>(R, I, s_rot + 72); rot1(R, I, s_rot + 84);
    cnot_ring_rev(R, I);

    // D2: fused phase rotation
    phases16(x_ang, ph);
#pragma unroll
    for (int k = 0; k < 8; k++) {
        float s0, c0, s1, c1;
        __sincosf(ph[2 * k], &s0, &c0);
        __sincosf(ph[2 * k + 1], &s1, &c1);
        ull c = PACK2(c0, c1), s = PACK2(s0, s1);
        ull nr = F2SUB(F2MUL(c, R[k]), F2MUL(s, I[k]));
        I[k] = F2FMA(s, R[k], F2MUL(c, I[k]));
        R[k] = nr;
    }

    // ansatz 2, layer 1 + ring; layer 2 rots; final ring folded into measurement
    rotL<4>(R, I, s_rot + 96);  rotL<2>(R, I, s_rot + 108);
    rotL<1>(R, I, s_rot + 120); rot1(R, I, s_rot + 132);
    cnot_ring(R, I);
    rotL<4>(R, I, s_rot + 144); rotL<2>(R, I, s_rot + 156);
    rotL<1>(R, I, s_rot + 168); rot1(R, I, s_rot + 180);

    // measurement with ring permutation folded into signs; scale 1/16
    float sv[8], dv[8];
#pragma unroll
    for (int k = 0; k < 8; k++) {
        ull P = F2FMA(I[k], I[k], F2MUL(R[k], R[k]));
        float2 p = UNPK(P);
        sv[k] = p.x + p.y;
        dv[k] = p.x - p.y;
    }
    float e0 = (dv[0] + dv[3] + dv[4] + dv[7]) - (dv[1] + dv[2] + dv[5] + dv[6]);
    float e1 = (sv[0] + sv[1] + sv[6] + sv[7]) - (sv[2] + sv[3] + sv[4] + sv[5]);
    float e2 = (sv[0] + sv[3] + sv[5] + sv[6]) - (sv[1] + sv[2] + sv[4] + sv[7]);
    float e3 = (dv[0] + dv[3] + dv[5] + dv[6]) - (dv[1] + dv[2] + dv[4] + dv[7]);
    const float sc = 1.0f / 16.0f;
    ev[0] = e0 * sc; ev[1] = e1 * sc; ev[2] = e2 * sc; ev[3] = e3 * sc;
}

__device__ __forceinline__ void kan_f(const float* hid, const float* W, float* oang) {
    float sl[4], x2[4], x3[4];
#pragma unroll
    for (int in = 0; in < 4; in++) {
        float x = hid[in];
        float e = __expf(-x);
        sl[in] = __fdividef(x, 1.0f + e);
        x2[in] = x * x;
        x3[in] = x2[in] * x;
    }
#pragma unroll
    for (int o = 0; o < 7; o++) {
        const float* w = W + o * 20;
        float acc = w[16];
#pragma unroll
        for (int in = 0; in < 4; in++) acc = fmaf(w[in], sl[in], acc);
#pragma unroll
        for (int in = 0; in < 4; in++) acc = fmaf(w[4 + in], hid[in], acc);
#pragma unroll
        for (int in = 0; in < 4; in++) acc = fmaf(w[8 + in], x2[in], acc);
#pragma unroll
        for (int in = 0; in < 4; in++) acc = fmaf(w[12 + in], x3[in], acc);
        oang[o] = acc;
    }
}

__global__ void __launch_bounds__(128, 1) qrnn_kernel(
    const float* __restrict__ inputs,      // [B, S, 4]
    const float* __restrict__ initial_t,   // [B, 7]
    const float* __restrict__ cw1,         // [16, 4]
    const float* __restrict__ cb1,         // [16]
    const float* __restrict__ cw2,         // [1, 16]
    const float* __restrict__ cb2,         // [1]
    float* __restrict__ out)               // [B]
{
    __shared__ __align__(16) ull s_rot[192];
    __shared__ float s_kan[140];
    int tid = threadIdx.x;
    const ull* grc = reinterpret_cast<const ull*>(g_rotc);
    for (int i = tid; i < 192; i += 128) s_rot[i] = grc[i];
    for (int i = tid; i < 140; i += 128) s_kan[i] = g_kan[i];
    __syncthreads();

    int b = blockIdx.x * blockDim.x + tid;

    float h_ang[7];
#pragma unroll
    for (int k = 0; k < 7; k++) h_ang[k] = initial_t[b * 7 + k];

    const float4* inp = reinterpret_cast<const float4*>(inputs) + (size_t)b * SLEN;

    float hid[4];
#pragma unroll 1
    for (int t = 0; t < SLEN; t++) {
        float4 xv = inp[t];
        float x_ang[7];
        x_ang[0] = xv.x; x_ang[1] = xv.y; x_ang[2] = xv.z; x_ang[3] = xv.w;
        x_ang[4] = (PI_F - xv.x) * (PI_F - xv.y);
        x_ang[5] = (PI_F - xv.y) * (PI_F - xv.z);
        x_ang[6] = (PI_F - xv.z) * (PI_F - xv.w);
        if (t > 0) kan_f(hid, s_kan, h_ang);
        qcell(h_ang, x_ang, s_rot, hid);
    }

    float o = cb2[0];
#pragma unroll 1
    for (int k = 0; k < 16; k++) {
        float a = cb1[k];
        a = fmaf(cw1[k * 4 + 0], hid[0], a);
        a = fmaf(cw1[k * 4 + 1], hid[1], a);
        a = fmaf(cw1[k * 4 + 2], hid[2], a);
        a = fmaf(cw1[k * 4 + 3], hid[3], a);
        o = fmaf(cw2[k], fmaxf(a, 0.0f), o);
    }
    out[b] = o;
}

extern "C" void kernel_launch(void* const* d_in, const int* in_sizes, int n_in,
                              void* d_out, int out_size) {
    const float* inputs    = (const float*)d_in[0];
    const float* initial_t = (const float*)d_in[1];
    const float* p1        = (const float*)d_in[2];
    const float* p2        = (const float*)d_in[3];
    const float* base_w    = (const float*)d_in[4];
    const float* spline_w  = (const float*)d_in[5];
    const float* cw1       = (const float*)d_in[6];
    const float* cb1       = (const float*)d_in[7];
    const float* cw2       = (const float*)d_in[8];
    const float* cb2       = (const float*)d_in[9];

    setup_kernel<<<1, 32>>>(p1, p2, base_w, spline_w);
    qrnn_kernel<<<BATCH / 128, 128>>>(inputs, initial_t,
                                      cw1, cb1, cw2, cb2, (float*)d_out);
}

// round 4
// speedup vs baseline: 3.4898x; 1.4562x over previous
#include <cuda_runtime.h>
#include <math.h>

#define SLEN 256
#define BATCH 16384
#define PI_F 3.14159265358979323846f
#define R2_F 0.70710678118654752440f

typedef unsigned long long ull;

// ---------- packed f32x2 primitives ----------
__device__ __forceinline__ ull F2MUL(ull a, ull b) {
    ull d; asm("mul.rn.f32x2 %0,%1,%2;" : "=l"(d) : "l"(a), "l"(b)); return d;
}
__device__ __forceinline__ ull F2FMA(ull a, ull b, ull c) {
    ull d; asm("fma.rn.f32x2 %0,%1,%2,%3;" : "=l"(d) : "l"(a), "l"(b), "l"(c)); return d;
}
__device__ __forceinline__ ull F2SUB(ull a, ull b) {
    ull d; asm("sub.rn.f32x2 %0,%1,%2;" : "=l"(d) : "l"(a), "l"(b)); return d;
}
__device__ __forceinline__ ull PACK2(float lo, float hi) {
    ull d; asm("mov.b64 %0,{%1,%2};" : "=l"(d) : "f"(lo), "f"(hi)); return d;
}
__device__ __forceinline__ float2 UNPK(ull v) {
    float2 r; asm("mov.b64 {%0,%1},%2;" : "=f"(r.x), "=f"(r.y) : "l"(v)); return r;
}
__device__ __forceinline__ ull SWAPH(ull v) {
    float2 r = UNPK(v); return PACK2(r.y, r.x);
}
__device__ __forceinline__ ull MIXLH(ull a, ull b) {   // (a.lo, b.hi)
    float2 x = UNPK(a), y = UNPK(b); return PACK2(x.x, y.y);
}
__device__ __forceinline__ ull SHFL64(ull v) {
    return __shfl_xor_sync(0xFFFFFFFFu, v, 1);
}
__device__ __forceinline__ ull HIXCH(ull v) {  // exchange hi lane with partner thread
    float2 f = UNPK(v);
    f.y = __shfl_xor_sync(0xFFFFFFFFu, f.y, 1);
    return PACK2(f.x, f.y);
}

// Gate constants: 4 layers x 42 ull slots:
//  [0..5]   q0-rot row for thread p=0 (self=a-row, partner=b)
//  [6..11]  q0-rot row for thread p=1 (self=e, partner=d)
//  [12..23] q1-rot (lane-dup, old rotL format)
//  [24..35] q2-rot (lane-dup)
//  [36..41] q3-rot (lane-mixed)
__device__ float2 g_rotc[168];
// KAN folded weights: 7 outputs x 20 (base[4], c1[4], c2[4], c3[4], c0sum, pad)
__device__ float g_kan[140];

__global__ void setup_kernel(const float* __restrict__ p1, const float* __restrict__ p2,
                             const float* __restrict__ base_w, const float* __restrict__ spline_w) {
    int t = threadIdx.x;
    if (t < 16) {
        int a = t >> 3, l = (t >> 2) & 1, q = t & 3;
        const float* p = a ? p2 : p1;
        float phi = p[l * 12 + q * 3 + 0];
        float th  = p[l * 12 + q * 3 + 1];
        float om  = p[l * 12 + q * 3 + 2];
        float st, ct; sincosf(0.5f * th, &st, &ct);
        float sp, cp; sincosf(0.5f * (phi + om), &sp, &cp);
        float sm, cm; sincosf(0.5f * (phi - om), &sm, &cm);
        float ar =  cp * ct, ai = -sp * ct;
        float br = -cm * st, bi = -sm * st;
        float dr =  cm * st, di = -sm * st;
        float er =  cp * ct, ei =  sp * ct;
        if (a == 0 && l == 1) {
            // fold the inter-ansatz H block: Rot' = H @ Rot
            float nar = (ar + dr) * R2_F, nai = (ai + di) * R2_F;
            float nbr = (br + er) * R2_F, nbi = (bi + ei) * R2_F;
            float ndr = (ar - dr) * R2_F, ndi = (ai - di) * R2_F;
            float ner = (br - er) * R2_F, nei = (bi - ei) * R2_F;
            ar = nar; ai = nai; br = nbr; bi = nbi;
            dr = ndr; di = ndi; er = ner; ei = nei;
        }
        int L = a * 2 + l;
        float2* base = g_rotc + L * 42;
        if (q == 0) {
            // row p=0: self = (ar,ai), partner = (br,bi)
            base[0] = make_float2(ar, ar);   base[1] = make_float2(-ai, -ai);
            base[2] = make_float2(ai, ai);   base[3] = make_float2(br, br);
            base[4] = make_float2(-bi, -bi); base[5] = make_float2(bi, bi);
            // row p=1: self = (er,ei), partner = (dr,di)
            base[6] = make_float2(er, er);   base[7] = make_float2(-ei, -ei);
            base[8] = make_float2(ei, ei);   base[9] = make_float2(dr, dr);
            base[10] = make_float2(-di, -di); base[11] = make_float2(di, di);
        } else if (q == 1 || q == 2) {
            float2* o = base + (q == 1 ? 12 : 24);
            o[0]  = make_float2(ar, ar);   o[1]  = make_float2(-ai, -ai);
            o[2]  = make_float2(br, br);   o[3]  = make_float2(-bi, -bi);
            o[4]  = make_float2(ai, ai);   o[5]  = make_float2(bi, bi);
            o[6]  = make_float2(dr, dr);   o[7]  = make_float2(-di, -di);
            o[8]  = make_float2(er, er);   o[9]  = make_float2(-ei, -ei);
            o[10] = make_float2(di, di);   o[11] = make_float2(ei, ei);
        } else {
            float2* o = base + 36;
            o[0] = make_float2(ar, er);
            o[1] = make_float2(br, dr);
            o[2] = make_float2(-ai, -ei);
            o[3] = make_float2(-bi, -di);
            o[4] = make_float2(ai, ei);
            o[5] = make_float2(bi, di);
        }
    }
    if (t == 16) {
        // B-spline bases on [-1,1) collapse to cubics: bs_j(x) = poly/48
        const float BP[4][4] = {
            {1.f, -3.f, 3.f, -1.f},
            {23.f, -15.f, -3.f, 3.f},
            {23.f, 15.f, -3.f, -3.f},
            {1.f, 3.f, 3.f, 1.f}
        };
        const float inv48 = 1.0f / 48.0f;
        for (int o = 0; o < 7; o++) {
            float c0sum = 0.f;
            for (int in = 0; in < 4; in++) {
                float P[4] = {0.f, 0.f, 0.f, 0.f};
                for (int j = 0; j < 4; j++) {
                    float w = spline_w[o * 16 + in * 4 + j] * inv48;
                    for (int k = 0; k < 4; k++) P[k] += w * BP[j][k];
                }
                g_kan[o * 20 + in]      = base_w[o * 4 + in];
                g_kan[o * 20 + 4 + in]  = P[1];
                g_kan[o * 20 + 8 + in]  = P[2];
                g_kan[o * 20 + 12 + in] = P[3];
                c0sum += P[0];
            }
            g_kan[o * 20 + 16] = c0sum;
        }
    }
}

// ---------------- split-state gates ----------------
// Per-thread state: R[4], I[4]. thread bit p = q0; pair bits: bit1=q1, bit0=q2;
// f32x2 lane = q3.

// One ansatz layer: rot q0 (cross-thread), rot q1, rot q2, rot q3
__device__ __forceinline__ void layer(ull* R, ull* I, const ull* m, int p) {
    // --- rot q0 (split across threads) ---
    {
        const ull* mq = m + p * 6;
        ull pr0 = SHFL64(R[0]), pr1 = SHFL64(R[1]), pr2 = SHFL64(R[2]), pr3 = SHFL64(R[3]);
        ull pi0 = SHFL64(I[0]), pi1 = SHFL64(I[1]), pi2 = SHFL64(I[2]), pi3 = SHFL64(I[3]);
        ull PR[4] = {pr0, pr1, pr2, pr3};
        ull PI[4] = {pi0, pi1, pi2, pi3};
        ull m0 = mq[0], m1 = mq[1], m2 = mq[2], m3 = mq[3], m4 = mq[4], m5 = mq[5];
#pragma unroll
        for (int k = 0; k < 4; k++) {
            ull xsr = R[k], xsi = I[k], xpr = PR[k], xpi = PI[k];
            ull t = F2MUL(m0, xsr); t = F2FMA(m1, xsi, t); t = F2FMA(m3, xpr, t); t = F2FMA(m4, xpi, t);
            ull u = F2MUL(m0, xsi); u = F2FMA(m2, xsr, u); u = F2FMA(m3, xpi, u); u = F2FMA(m5, xpr, u);
            R[k] = t; I[k] = u;
        }
    }
    // --- rot q1: pair-couples (0,2),(1,3) ---
    {
        const ull* q = m + 12;
#pragma unroll
        for (int k = 0; k < 2; k++) {
            const int j = k + 2;
            ull x0r = R[k], x0i = I[k], x1r = R[j], x1i = I[j];
            ull t;
            t = F2MUL(q[0], x0r); t = F2FMA(q[1], x0i, t); t = F2FMA(q[2], x1r, t); t = F2FMA(q[3], x1i, t); R[k] = t;
            t = F2MUL(q[0], x0i); t = F2FMA(q[4], x0r, t); t = F2FMA(q[2], x1i, t); t = F2FMA(q[5], x1r, t); I[k] = t;
            t = F2MUL(q[6], x0r); t = F2FMA(q[7], x0i, t); t = F2FMA(q[8], x1r, t); t = F2FMA(q[9], x1i, t); R[j] = t;
            t = F2MUL(q[6], x0i); t = F2FMA(q[10], x0r, t); t = F2FMA(q[8], x1i, t); t = F2FMA(q[11], x1r, t); I[j] = t;
        }
    }
    // --- rot q2: pair-couples (0,1),(2,3) ---
    {
        const ull* q = m + 24;
#pragma unroll
        for (int k = 0; k < 4; k += 2) {
            const int j = k + 1;
            ull x0r = R[k], x0i = I[k], x1r = R[j], x1i = I[j];
            ull t;
            t = F2MUL(q[0], x0r); t = F2FMA(q[1], x0i, t); t = F2FMA(q[2], x1r, t); t = F2FMA(q[3], x1i, t); R[k] = t;
            t = F2MUL(q[0], x0i); t = F2FMA(q[4], x0r, t); t = F2FMA(q[2], x1i, t); t = F2FMA(q[5], x1r, t); I[k] = t;
            t = F2MUL(q[6], x0r); t = F2FMA(q[7], x0i, t); t = F2FMA(q[8], x1r, t); t = F2FMA(q[9], x1i, t); R[j] = t;
            t = F2MUL(q[6], x0i); t = F2FMA(q[10], x0r, t); t = F2FMA(q[8], x1i, t); t = F2FMA(q[11], x1r, t); I[j] = t;
        }
    }
    // --- rot q3 (lane axis, lane-mixed constants) ---
    {
        const ull* q = m + 36;
        ull c0 = q[0], c1 = q[1], c2 = q[2], c3 = q[3], c4 = q[4], c5 = q[5];
#pragma unroll
        for (int k = 0; k < 4; k++) {
            ull pr = R[k], pi = I[k];
            ull prs = SWAPH(pr), pis = SWAPH(pi);
            ull t = F2MUL(c0, pr); t = F2FMA(c1, prs, t); t = F2FMA(c2, pi, t); t = F2FMA(c3, pis, t);
            ull u = F2MUL(c4, pr); u = F2FMA(c5, prs, u); u = F2FMA(c0, pi, u); u = F2FMA(c1, pis, u);
            R[k] = t; I[k] = u;
        }
    }
}

// normal ring: CNOT(q0,q1)(q1,q2)(q2,q3)(q3,q0)
__device__ __forceinline__ void ring_normal(ull* R, ull* I, int p) {
    // CNOT(q0,q1): thread p=1 swaps k 0<->2, 1<->3
    {
        ull r0 = R[0], r1 = R[1], r2 = R[2], r3 = R[3];
        R[0] = p ? r2 : r0; R[2] = p ? r0 : r2;
        R[1] = p ? r3 : r1; R[3] = p ? r1 : r3;
        ull i0 = I[0], i1 = I[1], i2 = I[2], i3 = I[3];
        I[0] = p ? i2 : i0; I[2] = p ? i0 : i2;
        I[1] = p ? i3 : i1; I[3] = p ? i1 : i3;
    }
    // CNOT(q1,q2): swap k 2<->3 (both threads)
    { ull t = R[2]; R[2] = R[3]; R[3] = t; t = I[2]; I[2] = I[3]; I[3] = t; }
    // CNOT(q2,q3): lane swap on k=1,3
    R[1] = SWAPH(R[1]); R[3] = SWAPH(R[3]);
    I[1] = SWAPH(I[1]); I[3] = SWAPH(I[3]);
    // CNOT(q3,q0): hi lanes exchange threads
#pragma unroll
    for (int k = 0; k < 4; k++) { R[k] = HIXCH(R[k]); I[k] = HIXCH(I[k]); }
}

// reversed ring: C(1,0) C(2,1) C(3,2) C(0,3)
__device__ __forceinline__ void ring_rev(ull* R, ull* I, int p) {
    // C(1,0): pairs k=2,3 exchange threads fully
    R[2] = SHFL64(R[2]); R[3] = SHFL64(R[3]);
    I[2] = SHFL64(I[2]); I[3] = SHFL64(I[3]);
    // C(2,1): swap k 1<->3
    { ull t = R[1]; R[1] = R[3]; R[3] = t; t = I[1]; I[1] = I[3]; I[3] = t; }
    // C(3,2): hi lanes swap bit0: MIXLH on (0,1) and (2,3)
    {
        ull a = R[0], b = R[1]; R[0] = MIXLH(a, b); R[1] = MIXLH(b, a);
        ull c = R[2], d = R[3]; R[2] = MIXLH(c, d); R[3] = MIXLH(d, c);
        ull e = I[0], f = I[1]; I[0] = MIXLH(e, f); I[1] = MIXLH(f, e);
        ull g = I[2], h = I[3]; I[2] = MIXLH(g, h); I[3] = MIXLH(h, g);
    }
    // C(0,3): thread p=1 swaps lanes everywhere
#pragma unroll
    for (int k = 0; k < 4; k++) {
        R[k] = p ? SWAPH(R[k]) : R[k];
        I[k] = p ? SWAPH(I[k]) : I[k];
    }
}

// 8 fused diagonal phases for this thread's half (q0 = p)
__device__ __forceinline__ void phases8(const float* ang, int p, float* ph) {
    float b0 = 0.5f * ang[0], b1 = 0.5f * ang[1], b2 = 0.5f * ang[2], b3 = 0.5f * ang[3];
    float b4 = 0.5f * ang[4], b5 = 0.5f * ang[5], b6 = 0.5f * ang[6];
    float t01 = b0 + b1, d01 = b0 - b1;
    float uA = p ? (d01 + b4) : (-t01 - b4);
    float uB = p ? (t01 - b4) : (-d01 + b4);
    float t23 = b2 + b3, d23 = b2 - b3;
    float e00 = -t23 - b6, e01 = -d23 + b6, e10 = d23 + b6, e11 = t23 - b6;
    ph[0] = uA + (e00 - b5); ph[1] = uA + (e01 - b5);
    ph[2] = uA + (e10 + b5); ph[3] = uA + (e11 + b5);
    ph[4] = uB + (e00 + b5); ph[5] = uB + (e01 + b5);
    ph[6] = uB + (e10 - b5); ph[7] = uB + (e11 - b5);
}

__device__ __forceinline__ void qcell(const float* h_ang, const float* x_ang,
                                      const ull* s_rot, int p, float sgnp, float* ev) {
    ull R[4], I[4];
    float ph[8];

    // D1 on uniform state: amps = e^{i phi} (scale 1/16 folded into measurement)
    phases8(h_ang, p, ph);
#pragma unroll
    for (int k = 0; k < 4; k++) {
        float s0, c0, s1, c1;
        __sincosf(ph[2 * k], &s0, &c0);
        __sincosf(ph[2 * k + 1], &s1, &c1);
        R[k] = PACK2(c0, c1); I[k] = PACK2(s0, s1);
    }

    // ansatz 1
    layer(R, I, s_rot, p);
    ring_normal(R, I, p);
    layer(R, I, s_rot + 42, p);   // H-folded layer
    ring_rev(R, I, p);

    // D2: fused phase rotation
    phases8(x_ang, p, ph);
#pragma unroll
    for (int k = 0; k < 4; k++) {
        float s0, c0, s1, c1;
        __sincosf(ph[2 * k], &s0, &c0);
        __sincosf(ph[2 * k + 1], &s1, &c1);
        ull c = PACK2(c0, c1), s = PACK2(s0, s1);
        ull nr = F2SUB(F2MUL(c, R[k]), F2MUL(s, I[k]));
        I[k] = F2FMA(s, R[k], F2MUL(c, I[k]));
        R[k] = nr;
    }

    // ansatz 2 (final ring folded into measurement signs)
    layer(R, I, s_rot + 84, p);
    ring_normal(R, I, p);
    layer(R, I, s_rot + 126, p);

    // measurement: per-thread partial combos, then 1-shuffle reduction
    float sv[4], dv[4];
#pragma unroll
    for (int k = 0; k < 4; k++) {
        ull P = F2FMA(I[k], I[k], F2MUL(R[k], R[k]));
        float2 f = UNPK(P);
        sv[k] = f.x + f.y;
        dv[k] = f.x - f.y;
    }
    float A = dv[0] - dv[1] - dv[2] + dv[3];
    float C = sv[0] + sv[1] - sv[2] - sv[3];
    float D = sv[0] - sv[1] - sv[2] + sv[3];
    float Ax = __shfl_xor_sync(0xFFFFFFFFu, A, 1);
    float Cx = __shfl_xor_sync(0xFFFFFFFFu, C, 1);
    float Dx = __shfl_xor_sync(0xFFFFFFFFu, D, 1);
    const float sc = 1.0f / 16.0f;
    ev[0] = (A + Ax) * sc;
    ev[1] = sgnp * (C - Cx) * sc;
    ev[2] = sgnp * (D - Dx) * sc;
    ev[3] = sgnp * (A - Ax) * sc;
}

__device__ __forceinline__ void kan_f(const float* hid, const float* W, float* oang) {
    float sl[4], x2[4], x3[4];
#pragma unroll
    for (int in = 0; in < 4; in++) {
        float x = hid[in];
        float e = __expf(-x);
        sl[in] = __fdividef(x, 1.0f + e);
        x2[in] = x * x;
        x3[in] = x2[in] * x;
    }
#pragma unroll
    for (int o = 0; o < 7; o++) {
        const float* w = W + o * 20;
        float acc = w[16];
#pragma unroll
        for (int in = 0; in < 4; in++) acc = fmaf(w[in], sl[in], acc);
#pragma unroll
        for (int in = 0; in < 4; in++) acc = fmaf(w[4 + in], hid[in], acc);
#pragma unroll
        for (int in = 0; in < 4; in++) acc = fmaf(w[8 + in], x2[in], acc);
#pragma unroll
        for (int in = 0; in < 4; in++) acc = fmaf(w[12 + in], x3[in], acc);
        oang[o] = acc;
    }
}

__global__ void __launch_bounds__(128, 2) qrnn_kernel(
    const float* __restrict__ inputs,      // [B, S, 4]
    const float* __restrict__ initial_t,   // [B, 7]
    const float* __restrict__ cw1,         // [16, 4]
    const float* __restrict__ cb1,         // [16]
    const float* __restrict__ cw2,         // [1, 16]
    const float* __restrict__ cb2,         // [1]
    float* __restrict__ out)               // [B]
{
    __shared__ __align__(16) ull s_rot[168];
    __shared__ float s_kan[140];
    int tid = threadIdx.x;
    const ull* grc = reinterpret_cast<const ull*>(g_rotc);
    for (int i = tid; i < 168; i += 128) s_rot[i] = grc[i];
    for (int i = tid; i < 140; i += 128) s_kan[i] = g_kan[i];
    __syncthreads();

    int gtid = blockIdx.x * blockDim.x + tid;
    int e = gtid >> 1;           // element index
    int p = gtid & 1;            // q0 parity held by this thread
    float sgnp = p ? -1.0f : 1.0f;

    float h_ang[7];
#pragma unroll
    for (int k = 0; k < 7; k++) h_ang[k] = initial_t[e * 7 + k];

    const float4* inp = reinterpret_cast<const float4*>(inputs) + (size_t)e * SLEN;

    float hid[4];
#pragma unroll 1
    for (int t = 0; t < SLEN; t++) {
        float4 xv = inp[t];
        float x_ang[7];
        x_ang[0] = xv.x; x_ang[1] = xv.y; x_ang[2] = xv.z; x_ang[3] = xv.w;
        x_ang[4] = (PI_F - xv.x) * (PI_F - xv.y);
        x_ang[5] = (PI_F - xv.y) * (PI_F - xv.z);
        x_ang[6] = (PI_F - xv.z) * (PI_F - xv.w);
        if (t > 0) kan_f(hid, s_kan, h_ang);
        qcell(h_ang, x_ang, s_rot, p, sgnp, hid);
    }

    float o = cb2[0];
#pragma unroll 1
    for (int k = 0; k < 16; k++) {
        float a = cb1[k];
        a = fmaf(cw1[k * 4 + 0], hid[0], a);
        a = fmaf(cw1[k * 4 + 1], hid[1], a);
        a = fmaf(cw1[k * 4 + 2], hid[2], a);
        a = fmaf(cw1[k * 4 + 3], hid[3], a);
        o = fmaf(cw2[k], fmaxf(a, 0.0f), o);
    }
    if (p == 0) out[e] = o;
}

extern "C" void kernel_launch(void* const* d_in, const int* in_sizes, int n_in,
                              void* d_out, int out_size) {
    const float* inputs    = (const float*)d_in[0];
    const float* initial_t = (const float*)d_in[1];
    const float* p1        = (const float*)d_in[2];
    const float* p2        = (const float*)d_in[3];
    const float* base_w    = (const float*)d_in[4];
    const float* spline_w  = (const float*)d_in[5];
    const float* cw1       = (const float*)d_in[6];
    const float* cb1       = (const float*)d_in[7];
    const float* cw2       = (const float*)d_in[8];
    const float* cb2       = (const float*)d_in[9];

    setup_kernel<<<1, 32>>>(p1, p2, base_w, spline_w);
    qrnn_kernel<<<(BATCH * 2) / 128, 128>>>(inputs, initial_t,
                                            cw1, cb1, cw2, cb2, (float*)d_out);
}